// round 2
// baseline (speedup 1.0000x reference)
#include <cuda_runtime.h>

#define NN   50000
#define TOPK 32
#define INC  128
#define OUTC 64
#define NEG_SLOPE 0.2f
#define BN_EPS 1e-5f

// ---------------- scratch (no allocations allowed) ----------------
__device__ float g_xlin[NN * OUTC];   // 12.8 MB
__device__ float g_si[NN];
__device__ float g_sj[NN];
__device__ float g_pre[NN * OUTC];    // pre-BN output, 12.8 MB
__device__ float g_sum[OUTC];
__device__ float g_sumsq[OUTC];
__device__ float g_scale[OUTC];
__device__ float g_shift[OUTC];
__device__ int   g_is64;

// ---------------- init: zero stats + detect index width ----------------
__global__ void k_init(const int* __restrict__ ei32) {
    int t = threadIdx.x;
    if (t < OUTC) { g_sum[t] = 0.f; g_sumsq[t] = 0.f; }
    if (t == 0) {
        // int64 little-endian: odd 32-bit words are the (zero) high halves.
        // int32: odd words are random src ids in [0,50000) -> ~surely nonzero.
        int any = 0;
        #pragma unroll 1
        for (int i = 1; i < 128; i += 2) any |= ei32[i];
        g_is64 = (any == 0) ? 1 : 0;
    }
}

// ---------------- GEMM: x_lin = x @ W^T  (M=50000, N=64, K=128) ----------------
// Tile: 128 rows x 64 cols per block, 256 threads, each thread 4x8 accumulators.
__global__ void __launch_bounds__(256) k_gemm(const float* __restrict__ x,
                                              const float* __restrict__ w) {
    __shared__ float Ws[INC][68];   // Ws[k][n] = w[n*128+k], pad 68 (float4-aligned rows)
    __shared__ float xs[16][132];   // xs[k][row], transposed chunk

    const int tid = threadIdx.x;
    const int m0  = blockIdx.x * 128;

    // load W transposed (coalesced global read)
    for (int idx = tid; idx < OUTC * INC; idx += 256) {
        int n = idx >> 7, k = idx & 127;
        Ws[k][n] = w[idx];
    }

    const int rg = tid & 31;   // row group (4 rows)
    const int cg = tid >> 5;   // col group (8 cols) == warp id

    float acc[4][8];
    #pragma unroll
    for (int i = 0; i < 4; i++)
        #pragma unroll
        for (int j = 0; j < 8; j++) acc[i][j] = 0.f;

    for (int kc = 0; kc < INC; kc += 16) {
        __syncthreads();
        // load 128 rows x 16 k, transposed into xs
        #pragma unroll
        for (int rr = 0; rr < 2; rr++) {
            int row = ((tid >> 2) & 63) + rr * 64;
            int k4  = (tid & 3) * 4;
            int gr  = m0 + row;
            float4 v = make_float4(0.f, 0.f, 0.f, 0.f);
            if (gr < NN) v = *(const float4*)&x[gr * INC + kc + k4];
            xs[k4 + 0][row] = v.x;
            xs[k4 + 1][row] = v.y;
            xs[k4 + 2][row] = v.z;
            xs[k4 + 3][row] = v.w;
        }
        __syncthreads();

        #pragma unroll
        for (int k = 0; k < 16; k++) {
            float4 a  = *(const float4*)&xs[k][rg * 4];
            float4 b0 = *(const float4*)&Ws[kc + k][cg * 8];
            float4 b1 = *(const float4*)&Ws[kc + k][cg * 8 + 4];
            float av[4] = {a.x, a.y, a.z, a.w};
            float bv[8] = {b0.x, b0.y, b0.z, b0.w, b1.x, b1.y, b1.z, b1.w};
            #pragma unroll
            for (int i = 0; i < 4; i++)
                #pragma unroll
                for (int j = 0; j < 8; j++)
                    acc[i][j] = fmaf(av[i], bv[j], acc[i][j]);
        }
    }

    #pragma unroll
    for (int i = 0; i < 4; i++) {
        int m = m0 + rg * 4 + i;
        if (m < NN) {
            float4 o0 = make_float4(acc[i][0], acc[i][1], acc[i][2], acc[i][3]);
            float4 o1 = make_float4(acc[i][4], acc[i][5], acc[i][6], acc[i][7]);
            *(float4*)&g_xlin[m * OUTC + cg * 8]     = o0;
            *(float4*)&g_xlin[m * OUTC + cg * 8 + 4] = o1;
        }
    }
}

// ---------------- per-node attention scalars ----------------
__global__ void __launch_bounds__(256) k_scal(const float* __restrict__ emb,
                                              const float* __restrict__ ai,
                                              const float* __restrict__ aj,
                                              const float* __restrict__ aei,
                                              const float* __restrict__ aej) {
    int wrow = blockIdx.x * 8 + (threadIdx.x >> 5);
    int lane = threadIdx.x & 31;
    if (wrow >= NN) return;
    float x0 = g_xlin[wrow * OUTC + lane];
    float x1 = g_xlin[wrow * OUTC + 32 + lane];
    float e0 = emb[wrow * OUTC + lane];
    float e1 = emb[wrow * OUTC + 32 + lane];
    float si = x0 * ai[lane] + x1 * ai[lane + 32] + e0 * aei[lane] + e1 * aei[lane + 32];
    float sj = x0 * aj[lane] + x1 * aj[lane + 32] + e0 * aej[lane] + e1 * aej[lane + 32];
    #pragma unroll
    for (int o = 16; o; o >>= 1) {
        si += __shfl_xor_sync(0xffffffffu, si, o);
        sj += __shfl_xor_sync(0xffffffffu, sj, o);
    }
    if (lane == 0) { g_si[wrow] = si; g_sj[wrow] = sj; }
}

// ---------------- softmax + weighted aggregation (one block per node) ----------------
__global__ void __launch_bounds__(64) k_agg(const void* __restrict__ ei,
                                            const float* __restrict__ bias) {
    const int n   = blockIdx.x;
    const int tid = threadIdx.x;
    __shared__ float sw[33];
    __shared__ int   srcs[32];

    if (tid < 32) {
        int s;
        if (g_is64) s = (int)((const long long*)ei)[(long long)n * TOPK + tid];
        else        s = ((const int*)ei)[n * TOPK + tid];
        srcs[tid] = s;
        float si = g_si[n];
        float a = si + g_sj[s];
        a = (a >= 0.f) ? a : NEG_SLOPE * a;
        float aself = 0.f;
        if (tid == 0) {
            float t = si + g_sj[n];
            aself = (t >= 0.f) ? t : NEG_SLOPE * t;
        }
        float m = (tid == 0) ? fmaxf(a, aself) : a;
        #pragma unroll
        for (int o = 16; o; o >>= 1) m = fmaxf(m, __shfl_xor_sync(0xffffffffu, m, o));
        float ex  = __expf(a - m);
        float exs = (tid == 0) ? __expf(aself - m) : 0.f;
        float ssum = ex + exs;
        #pragma unroll
        for (int o = 16; o; o >>= 1) ssum += __shfl_xor_sync(0xffffffffu, ssum, o);
        float inv = 1.f / (ssum + 1e-16f);
        sw[tid] = ex * inv;
        if (tid == 0) sw[32] = exs * inv;
    }
    __syncthreads();

    // lane tid = channel; gather 33 rows of x_lin (coalesced 256B per warp-pair)
    float acc = 0.f;
    #pragma unroll
    for (int e = 0; e < TOPK; e++)
        acc = fmaf(sw[e], g_xlin[srcs[e] * OUTC + tid], acc);
    acc = fmaf(sw[32], g_xlin[n * OUTC + tid], acc);

    g_pre[n * OUTC + tid] = acc + bias[tid];
}

// ---------------- BN reduction ----------------
__global__ void __launch_bounds__(256) k_red() {
    __shared__ float ssum[4][OUTC];
    __shared__ float ssq[4][OUTC];
    int c = threadIdx.x & 63, q = threadIdx.x >> 6;
    float s = 0.f, s2 = 0.f;
    for (int r = blockIdx.x * 4 + q; r < NN; r += gridDim.x * 4) {
        float v = g_pre[r * OUTC + c];
        s += v;
        s2 = fmaf(v, v, s2);
    }
    ssum[q][c] = s; ssq[q][c] = s2;
    __syncthreads();
    if (q == 0) {
        s  = ssum[0][c] + ssum[1][c] + ssum[2][c] + ssum[3][c];
        s2 = ssq[0][c] + ssq[1][c] + ssq[2][c] + ssq[3][c];
        atomicAdd(&g_sum[c], s);
        atomicAdd(&g_sumsq[c], s2);
    }
}

// ---------------- BN stats -> scale/shift ----------------
__global__ void k_stats(const float* __restrict__ gamma,
                        const float* __restrict__ beta) {
    int c = threadIdx.x;
    float mean = g_sum[c] * (1.f / NN);
    float var  = g_sumsq[c] * (1.f / NN) - mean * mean;
    float inv  = rsqrtf(var + BN_EPS);
    float sc   = gamma[c] * inv;
    g_scale[c] = sc;
    g_shift[c] = beta[c] - mean * sc;
}

// ---------------- apply BN + ReLU ----------------
__global__ void __launch_bounds__(256) k_bn(float* __restrict__ out) {
    int i4 = blockIdx.x * 256 + threadIdx.x;
    if (i4 < NN * OUTC / 4) {
        int base = i4 * 4;
        int c = base & 63;
        float4 v  = *(const float4*)&g_pre[base];
        float4 sc = *(const float4*)&g_scale[c];
        float4 sh = *(const float4*)&g_shift[c];
        v.x = fmaxf(fmaf(v.x, sc.x, sh.x), 0.f);
        v.y = fmaxf(fmaf(v.y, sc.y, sh.y), 0.f);
        v.z = fmaxf(fmaf(v.z, sc.z, sh.z), 0.f);
        v.w = fmaxf(fmaf(v.w, sc.w, sh.w), 0.f);
        *(float4*)&out[base] = v;
    }
}

// ---------------- launch ----------------
extern "C" void kernel_launch(void* const* d_in, const int* in_sizes, int n_in,
                              void* d_out, int out_size) {
    const float* x    = (const float*)d_in[0];
    const float* emb  = (const float*)d_in[1];
    const void*  ei   = d_in[2];
    const float* linw = (const float*)d_in[3];
    const float* ai   = (const float*)d_in[4];
    const float* aj   = (const float*)d_in[5];
    const float* aei  = (const float*)d_in[6];
    const float* aej  = (const float*)d_in[7];
    const float* bias = (const float*)d_in[8];
    const float* gam  = (const float*)d_in[9];
    const float* bet  = (const float*)d_in[10];
    float* out = (float*)d_out;

    k_init<<<1, 64>>>((const int*)ei);
    k_gemm<<<(NN + 127) / 128, 256>>>(x, linw);
    k_scal<<<(NN + 7) / 8, 256>>>(emb, ai, aj, aei, aej);
    k_agg<<<NN, 64>>>(ei, bias);
    k_red<<<500, 256>>>();
    k_stats<<<1, OUTC>>>(gam, bet);
    k_bn<<<(NN * OUTC / 4 + 255) / 256, 256>>>(out);
}